// round 17
// baseline (speedup 1.0000x reference)
#include <cuda_runtime.h>
#include <cstdint>

// Problem constants (fixed shapes per reference)
#define NSPANS 4096
#define TMAX   16
#define HDIM   768
#define H4     192          // HDIM / 4 (float4 lanes per row)
#define R4     576          // 3 * H4 = float4 per span repr (half output row)
#define HALF_BYTES (R4 * 16)   // 9216 B contiguous half-row
#define NPAIRS 16384
#define SL     2048         // S * L
#define CAP    96           // bucket capacity per span (mean 8, sigma 2.9)

// Bucket scratch. Device globals are zero-initialized at load; scatter_kernel
// re-zeroes cursor after use, so every launch/replay sees it zeroed.
__device__ int g_cursor[NSPANS];
__device__ int g_bucket[NSPANS * CAP];   // packed entry: p*2 + side

// ---------------------------------------------------------------- fill
// One thread per pair pushes both (pair, side) entries into the spans'
// buckets. Slot order is atomic-nondeterministic, but each entry encodes
// its own output slot, so the final output is deterministic.
__global__ __launch_bounds__(128) void fill_kernel(
    const int* __restrict__ pair_i,
    const int* __restrict__ pair_j)
{
    const int p  = blockIdx.x * 128 + threadIdx.x;   // 0..NPAIRS-1
    const int si = __ldg(pair_i + p);
    const int sj = __ldg(pair_j + p);
    const int posi = atomicAdd(&g_cursor[si], 1);
    const int posj = atomicAdd(&g_cursor[sj], 1);
    if (posi < CAP) g_bucket[si * CAP + posi] = p * 2;
    if (posj < CAP) g_bucket[sj * CAP + posj] = p * 2 + 1;
}

// ---------------------------------------------------------------- scatter
// One block of 192 threads per span. Thread t computes lane t of the repr
// (vf/vl captured inside the 16-wide clamped mean loop -> 16 hidden loads),
// stages the 9216-B half-row in SMEM once, then ONE thread issues a single
// cp.async.bulk (TMA 1D bulk store) per (pair, side) occurrence — the TMA
// engine streams whole contiguous half-rows, replacing 576 STG.128 per entry
// with one instruction.
__global__ __launch_bounds__(192) void scatter_kernel(
    const float* __restrict__ hidden,
    const int*   __restrict__ span_doc,
    const int*   __restrict__ span_tok,
    const int*   __restrict__ span_len,
    float4*      __restrict__ out)
{
    const int n = blockIdx.x;
    const int t = threadIdx.x;        // 0..191

    __shared__ int s_tok[TMAX];
    __shared__ int s_ent[CAP];
    __shared__ __align__(16) float4 s_buf[R4];   // 9216 B half-row

    const int cnt0 = g_cursor[n];               // uniform broadcast load
    const int cnt  = (cnt0 < CAP) ? cnt0 : CAP;

    if (t < TMAX) s_tok[t] = __ldg(span_tok + n * TMAX + t);
    if (t >= 64 && t - 64 < cnt) s_ent[t - 64] = g_bucket[n * CAP + (t - 64)];
    __syncthreads();

    const int doc   = __ldg(span_doc + n);
    const int len   = __ldg(span_len + n);   // 1..16
    const int lenm1 = len - 1;

    const float4* __restrict__ base =
        reinterpret_cast<const float4*>(hidden) + (size_t)doc * SL * H4;

    float4 vf = make_float4(0.f, 0.f, 0.f, 0.f);
    float4 vl = vf;
    float4 acc = vf;

    #pragma unroll
    for (int k = 0; k < TMAX; ++k) {
        const int tt = (k < len) ? k : lenm1;  // clamp -> L1-hit duplicate
        const float w = (k < len) ? 1.0f : 0.0f;
        const float4 g = __ldg(base + (size_t)s_tok[tt] * H4 + t);
        if (k == 0) vf = g;                    // first row
        if (k == lenm1) vl = g;                // last row
        acc.x += g.x * w; acc.y += g.y * w;
        acc.z += g.z * w; acc.w += g.w * w;
    }
    const float inv = 1.0f / (float)len;
    const float4 vm = make_float4(acc.x * inv, acc.y * inv,
                                  acc.z * inv, acc.w * inv);

    // Stage the half-row [first | mean | last] in SMEM.
    s_buf[t]       = vf;
    s_buf[192 + t] = vm;
    s_buf[384 + t] = vl;
    __syncthreads();

    if (t == 0) {
        // Order generic SMEM writes before async-proxy reads.
        asm volatile("fence.proxy.async.shared::cta;" ::: "memory");
        uint32_t src;
        asm("{ .reg .u64 a; cvta.to.shared.u64 a, %1; cvt.u32.u64 %0, a; }"
            : "=r"(src) : "l"((const void*)s_buf));
        for (int k = 0; k < cnt; ++k) {
            const int e = s_ent[k];
            const uint64_t dst = (uint64_t)(out + (size_t)e * R4);
            asm volatile(
                "cp.async.bulk.global.shared::cta.bulk_group [%0], [%1], %2;"
                :: "l"(dst), "r"(src), "r"((int)HALF_BYTES) : "memory");
        }
        asm volatile("cp.async.bulk.commit_group;" ::: "memory");
        asm volatile("cp.async.bulk.wait_group 0;" ::: "memory");
        // Reset cursor for the next graph replay (all threads already read cnt).
        g_cursor[n] = 0;
    }
}

extern "C" void kernel_launch(void* const* d_in, const int* in_sizes, int n_in,
                              void* d_out, int out_size)
{
    const float* hidden   = (const float*)d_in[0];
    const int*   span_doc = (const int*)  d_in[1];
    const int*   span_tok = (const int*)  d_in[2];
    const int*   span_len = (const int*)  d_in[3];
    const int*   pair_i   = (const int*)  d_in[4];
    const int*   pair_j   = (const int*)  d_in[5];
    float4*      out      = (float4*)     d_out;

    fill_kernel<<<NPAIRS / 128, 128>>>(pair_i, pair_j);
    scatter_kernel<<<NSPANS, 192>>>(hidden, span_doc, span_tok, span_len, out);
}